// round 14
// baseline (speedup 1.0000x reference)
#include <cuda_runtime.h>
#include <cuda_bf16.h>
#include <math.h>
#include <stdint.h>

// ---------------- problem constants ----------------
#define BATCH 2
#define GRID_DIM 32
#define C_DIM 192
#define HEADS 6
#define HD 32
#define NTOK 64
#define NWIN 1024
#define M_TOT (NWIN * NTOK)
#define HID 768
#define SHIFT_AMT 2

// GEMM smem: 3 stages of A(256x40) + B(64x40), bf16
#define GEMM_SMEM_BYTES (3 * (256 * 40 + 64 * 40) * 2)

// ---------------- scratch (device globals; no allocs) ----------------
__device__ __nv_bfloat16 g_xw[M_TOT * C_DIM];
__device__ __nv_bfloat16 g_qkv[3 * NWIN * HEADS * NTOK * HD]; // q pre-scaled
__device__ __nv_bfloat16 g_attnout[M_TOT * C_DIM];
__device__ float         g_xo[M_TOT * C_DIM];
__device__ __nv_bfloat16 g_xn2[M_TOT * C_DIM];
__device__ __nv_bfloat16 g_h1[M_TOT * HID];
// transposed bf16 weights [N][K]
__device__ __nv_bfloat16 g_wqkvT[576 * 192];
__device__ __nv_bfloat16 g_woT[192 * 192];
__device__ __nv_bfloat16 g_w1T[768 * 192];
__device__ __nv_bfloat16 g_w2T[192 * 768];

// ---------------- helpers ----------------
__device__ __forceinline__ float gelu_exact(float v) {
    return 0.5f * v * (1.0f + erff(v * 0.70710678118654752f));
}
__device__ __forceinline__ void mma_bf16(float (&c)[4], const uint32_t (&a)[4],
                                         const uint32_t b0, const uint32_t b1) {
    asm volatile(
        "mma.sync.aligned.m16n8k16.row.col.f32.bf16.bf16.f32 "
        "{%0,%1,%2,%3}, {%4,%5,%6,%7}, {%8,%9}, {%0,%1,%2,%3};"
        : "+f"(c[0]), "+f"(c[1]), "+f"(c[2]), "+f"(c[3])
        : "r"(a[0]), "r"(a[1]), "r"(a[2]), "r"(a[3]), "r"(b0), "r"(b1));
}
__device__ __forceinline__ void mma_bf16v(float (&c)[4], const uint32_t (&a)[4],
                                          const uint32_t (&b)[2]) {
    mma_bf16(c, a, b[0], b[1]);
}
__device__ __forceinline__ void ldm_x4(uint32_t (&r)[4], uint32_t addr) {
    asm volatile("ldmatrix.sync.aligned.m8n8.x4.shared.b16 {%0,%1,%2,%3}, [%4];"
                 : "=r"(r[0]), "=r"(r[1]), "=r"(r[2]), "=r"(r[3]) : "r"(addr));
}
__device__ __forceinline__ uint32_t packbf2(float a, float b) {
    __nv_bfloat162 t = __floats2bfloat162_rn(a, b);
    return *(uint32_t*)&t;
}
__device__ __forceinline__ uint32_t smem_u32(const void* p) {
    return (uint32_t)__cvta_generic_to_shared(p);
}
#define CP16(dst, src) \
    asm volatile("cp.async.cg.shared.global [%0], [%1], 16;" :: "r"(dst), "l"(src))
#define CP_COMMIT() asm volatile("cp.async.commit_group;")
#define CP_WAIT1()  asm volatile("cp.async.wait_group 1;")

__device__ __forceinline__ int winrow_to_orig(int t) {
    int wi = t >> 6, n = t & 63;
    int b  = wi >> 9;
    int Hb = (wi >> 6) & 7, Wb = (wi >> 3) & 7, Db = wi & 7;
    int i = n >> 4, j = (n >> 2) & 3, k = n & 3;
    int h = ((Hb << 2) + i + SHIFT_AMT) & 31;
    int w = ((Wb << 2) + j + SHIFT_AMT) & 31;
    int d = ((Db << 2) + k + SHIFT_AMT) & 31;
    return (((b * 32 + h) * 32 + w) * 32 + d);
}

// ---------------- weight prep: all four fp32 [K][N] -> bf16 [N][K] --------
#define W0 (576 * 192)
#define W1 (192 * 192)
#define W2 (768 * 192)
#define W3 (192 * 768)
__global__ __launch_bounds__(256) void prep_all(const float* __restrict__ wqkv,
                                                const float* __restrict__ wo,
                                                const float* __restrict__ w1,
                                                const float* __restrict__ w2) {
    int i = blockIdx.x * 256 + threadIdx.x;
    const float* src;
    __nv_bfloat16* dst;
    int K, N;
    if (i < W0)                       { src = wqkv; dst = g_wqkvT; K = 192; N = 576; }
    else if ((i -= W0) < W1)          { src = wo;   dst = g_woT;   K = 192; N = 192; }
    else if ((i -= W1) < W2)          { src = w1;   dst = g_w1T;   K = 192; N = 768; }
    else if ((i -= W2) < W3)          { src = w2;   dst = g_w2T;   K = 768; N = 192; }
    else return;
    int n = i / K, k = i - n * K;
    dst[i] = __float2bfloat16(src[k * N + n]);
}

// ---------------- LN kernels (warp per token), bf16 output ----------------
__global__ __launch_bounds__(256) void ln_kernel(const float* __restrict__ xin,
                                                 const float* __restrict__ gma,
                                                 const float* __restrict__ bta,
                                                 int mode) {
    int warp = threadIdx.x >> 5, lane = threadIdx.x & 31;
    int t = blockIdx.x * 8 + warp;
    const float* src;
    __nv_bfloat16* dst;
    if (mode == 0) {
        src = xin + (size_t)winrow_to_orig(t) * C_DIM;
        dst = g_xw + (size_t)t * C_DIM;
    } else {
        src = g_xo + (size_t)t * C_DIM;
        dst = g_xn2 + (size_t)t * C_DIM;
    }
    float v[6];
    float s = 0.f;
#pragma unroll
    for (int k = 0; k < 6; k++) { v[k] = src[lane + 32 * k]; s += v[k]; }
#pragma unroll
    for (int o = 16; o > 0; o >>= 1) s += __shfl_xor_sync(0xffffffffu, s, o);
    float mean = s * (1.0f / C_DIM);
    float q = 0.f;
#pragma unroll
    for (int k = 0; k < 6; k++) { float d = v[k] - mean; q += d * d; }
#pragma unroll
    for (int o = 16; o > 0; o >>= 1) q += __shfl_xor_sync(0xffffffffu, q, o);
    float rstd = rsqrtf(q * (1.0f / C_DIM) + 1e-5f);
#pragma unroll
    for (int k = 0; k < 6; k++) {
        int c = lane + 32 * k;
        dst[c] = __float2bfloat16((v[k] - mean) * rstd * gma[c] + bta[c]);
    }
}

// ---------------- bf16 GEMM v3: 256x64 tile, warp tile 64x32 --------------
// 256 threads = 8 warps (4x2). 3-stage cp.async + ldmatrix. Dynamic smem.
__global__ __launch_bounds__(256) void gemm_bf16(const __nv_bfloat16* __restrict__ BwT,
                                                 const float* __restrict__ bias,
                                                 const float* __restrict__ xres,
                                                 float* __restrict__ dout,
                                                 int K, int N, int mode) {
    const __nv_bfloat16* A = (mode == 0) ? g_xw
                           : (mode == 1) ? g_attnout
                           : (mode == 2) ? g_xn2
                                         : g_h1;
    extern __shared__ __nv_bfloat16 smemDyn[];
    __nv_bfloat16* AsH = smemDyn;                 // 3 stages of 256*40
    __nv_bfloat16* BsH = smemDyn + 3 * 256 * 40;  // 3 stages of 64*40
#define AS(s) (AsH + (s) * 256 * 40)
#define BS(s) (BsH + (s) * 64 * 40)

    int tid = threadIdx.x;
    int warp = tid >> 5, lane = tid & 31;
    int gid = lane >> 2, tig = lane & 3;
    int warpM = warp & 3, warpN = warp >> 2;
    int row0 = blockIdx.y * 256, col0 = blockIdx.x * 64;

    // cp.async coordinates: A row per thread (4 chunks), B one chunk
    int bRow = tid >> 2, bCol = (tid & 3) * 8;
    const __nv_bfloat16* aSrc = A + (size_t)(row0 + tid) * K;
    const __nv_bfloat16* bSrc = BwT + (size_t)(col0 + bRow) * K + bCol;

    // ldmatrix offsets
    int aKoff = (lane >> 4) << 3;
    int aLdmRow[4];
#pragma unroll
    for (int mt = 0; mt < 4; mt++)
        aLdmRow[mt] = (warpM * 64 + mt * 16 + (lane & 15)) * 40 + aKoff;
    int bKoff = ((lane >> 3) & 1) << 3;
    int bLdmRow = (warpN * 32 + ((lane >> 4) << 3) + (lane & 7)) * 40 + bKoff;

    int NK = K >> 5;

    float acc[4][4][4];
#pragma unroll
    for (int mt = 0; mt < 4; mt++)
#pragma unroll
        for (int nt = 0; nt < 4; nt++)
#pragma unroll
            for (int i = 0; i < 4; i++) acc[mt][nt][i] = 0.f;

    // prologue: stages 0,1
#pragma unroll
    for (int s = 0; s < 2; s++) {
        uint32_t ad = smem_u32(AS(s) + tid * 40);
        const __nv_bfloat16* as = aSrc + s * 32;
#pragma unroll
        for (int c = 0; c < 4; c++) CP16(ad + c * 16, as + c * 8);
        uint32_t bd = smem_u32(BS(s) + bRow * 40 + bCol);
        CP16(bd, bSrc + s * 32);
        CP_COMMIT();
    }

    for (int ki = 0; ki < NK; ki++) {
        CP_WAIT1();
        __syncthreads();
        int kn = ki + 2;
        if (kn < NK) {
            int st = kn % 3;
            uint32_t ad = smem_u32(AS(st) + tid * 40);
            const __nv_bfloat16* as = aSrc + kn * 32;
#pragma unroll
            for (int c = 0; c < 4; c++) CP16(ad + c * 16, as + c * 8);
            uint32_t bd = smem_u32(BS(st) + bRow * 40 + bCol);
            CP16(bd, bSrc + kn * 32);
        }
        CP_COMMIT();

        int s = ki % 3;
        uint32_t aBase = smem_u32(AS(s));
        uint32_t bBase = smem_u32(BS(s));
#pragma unroll
        for (int kk = 0; kk < 32; kk += 16) {
            uint32_t afr[4][4];
#pragma unroll
            for (int mt = 0; mt < 4; mt++)
                ldm_x4(afr[mt], aBase + (aLdmRow[mt] + kk) * 2);
#pragma unroll
            for (int p = 0; p < 2; p++) {
                uint32_t bfr[4];
                ldm_x4(bfr, bBase + (bLdmRow + p * 16 * 40 + kk) * 2);
#pragma unroll
                for (int mt = 0; mt < 4; mt++) {
                    mma_bf16(acc[mt][2 * p + 0], afr[mt], bfr[0], bfr[1]);
                    mma_bf16(acc[mt][2 * p + 1], afr[mt], bfr[2], bfr[3]);
                }
            }
        }
    }

    const float QK_SCALE = 0.17677669529663687f;
#pragma unroll
    for (int mt = 0; mt < 4; mt++) {
        int rbase = row0 + warpM * 64 + mt * 16 + gid;
#pragma unroll
        for (int half = 0; half < 2; half++) {
            int row = rbase + half * 8;
            int obase1 = 0;
            if (mode == 1) obase1 = winrow_to_orig(row) * C_DIM;
#pragma unroll
            for (int nt = 0; nt < 4; nt++) {
                int col = col0 + warpN * 32 + nt * 8 + 2 * tig;
                float v0 = acc[mt][nt][half * 2 + 0] + bias[col];
                float v1 = acc[mt][nt][half * 2 + 1] + bias[col + 1];
                if (mode == 0) {
                    int wi = row >> 6, n = row & 63;
                    int which = col / 192;
                    int rem = col - which * 192;
                    int head = rem >> 5, hdi = rem & 31;
                    float sc = (which == 0) ? QK_SCALE : 1.0f;
                    uint32_t* p = (uint32_t*)&g_qkv[(((which * NWIN + wi) * HEADS + head) << 11) + (n << 5) + hdi];
                    *p = packbf2(v0 * sc, v1 * sc);
                } else if (mode == 1) {
                    float* p = &g_xo[obase1 + col];
                    const float* r = &xres[obase1 + col];
                    *(float2*)p = make_float2(v0 + r[0], v1 + r[1]);
                } else if (mode == 2) {
                    uint32_t* p = (uint32_t*)&g_h1[(size_t)row * HID + col];
                    *p = packbf2(gelu_exact(v0), gelu_exact(v1));
                } else {
                    size_t o = (size_t)row * C_DIM + col;
                    *(float2*)&dout[o] = make_float2(v0 + g_xo[o], v1 + g_xo[o + 1]);
                }
            }
        }
    }
#undef AS
#undef BS
}

// ---------------- attention: tensor-core, 1 block per (window, head) -------
__global__ __launch_bounds__(128) void attn_kernel(const float* __restrict__ bias_table) {
    __shared__ __nv_bfloat16 sQ[64 * 40];
    __shared__ __nv_bfloat16 sK[64 * 40];
    __shared__ __nv_bfloat16 sVT[32 * 72];
    __shared__ float sBias[343];
    __shared__ unsigned char sReg[64];

    int wi = blockIdx.x / HEADS, head = blockIdx.x % HEADS;
    int tid = threadIdx.x;
    int warp = tid >> 5, lane = tid & 31;
    int g = lane >> 2, q4 = lane & 3;

    const __nv_bfloat16* Qg = g_qkv + (((0 * NWIN + wi) * HEADS + head) << 11);
    const __nv_bfloat16* Kg = g_qkv + (((1 * NWIN + wi) * HEADS + head) << 11);
    const __nv_bfloat16* Vg = g_qkv + (((2 * NWIN + wi) * HEADS + head) << 11);

#pragma unroll
    for (int i = tid; i < 256; i += 128) {
        int r = i >> 2, c = (i & 3) * 8;
        *(uint4*)&sQ[r * 40 + c] = *(const uint4*)&Qg[r * 32 + c];
        *(uint4*)&sK[r * 40 + c] = *(const uint4*)&Kg[r * 32 + c];
        uint4 v = *(const uint4*)&Vg[r * 32 + c];
        __nv_bfloat16 tmp[8];
        *(uint4*)tmp = v;
#pragma unroll
        for (int j = 0; j < 8; j++) sVT[(c + j) * 72 + r] = tmp[j];
    }
    if (tid < 64) {
        int Hb = (wi >> 6) & 7, Wb = (wi >> 3) & 7, Db = wi & 7;
        int ih = tid >> 4, iw = (tid >> 2) & 3, id = tid & 3;
        int rh = (Hb == 7) ? (ih >= 2 ? 2 : 1) : 0;
        int rw = (Wb == 7) ? (iw >= 2 ? 2 : 1) : 0;
        int rd = (Db == 7) ? (id >= 2 ? 2 : 1) : 0;
        sReg[tid] = (unsigned char)(rh * 9 + rw * 3 + rd);
    }
    for (int i = tid; i < 343; i += 128) sBias[i] = bias_table[i * HEADS + head];
    __syncthreads();

    int m0 = warp * 16;
    uint32_t af[2][4];
#pragma unroll
    for (int kt = 0; kt < 2; kt++) {
        int kk = kt * 16;
        af[kt][0] = *(const uint32_t*)&sQ[(m0 + g) * 40 + kk + 2 * q4];
        af[kt][1] = *(const uint32_t*)&sQ[(m0 + g + 8) * 40 + kk + 2 * q4];
        af[kt][2] = *(const uint32_t*)&sQ[(m0 + g) * 40 + kk + 8 + 2 * q4];
        af[kt][3] = *(const uint32_t*)&sQ[(m0 + g + 8) * 40 + kk + 8 + 2 * q4];
    }
    float c[8][4];
#pragma unroll
    for (int nt = 0; nt < 8; nt++)
#pragma unroll
        for (int i = 0; i < 4; i++) c[nt][i] = 0.f;
#pragma unroll
    for (int nt = 0; nt < 8; nt++) {
#pragma unroll
        for (int kt = 0; kt < 2; kt++) {
            uint32_t bf[2];
            bf[0] = *(const uint32_t*)&sK[(nt * 8 + g) * 40 + kt * 16 + 2 * q4];
            bf[1] = *(const uint32_t*)&sK[(nt * 8 + g) * 40 + kt * 16 + 8 + 2 * q4];
            mma_bf16v(c[nt], af[kt], bf);
        }
    }

    int i0 = m0 + g, i1 = i0 + 8;
    int base0 = (i0 >> 4) * 49 + ((i0 >> 2) & 3) * 7 + (i0 & 3);
    int base1 = (i1 >> 4) * 49 + ((i1 >> 2) & 3) * 7 + (i1 & 3);
    int r0 = sReg[i0], r1 = sReg[i1];
#pragma unroll
    for (int nt = 0; nt < 8; nt++) {
#pragma unroll
        for (int e = 0; e < 2; e++) {
            int j = nt * 8 + 2 * q4 + e;
            int jb = (j >> 4) * 49 + ((j >> 2) & 3) * 7 + (j & 3);
            int rj = sReg[j];
            c[nt][e]     += sBias[base0 - jb + 171] + ((r0 == rj) ? 0.f : -100.f);
            c[nt][2 + e] += sBias[base1 - jb + 171] + ((r1 == rj) ? 0.f : -100.f);
        }
    }

    float mx0 = -1e30f, mx1 = -1e30f;
#pragma unroll
    for (int nt = 0; nt < 8; nt++) {
        mx0 = fmaxf(mx0, fmaxf(c[nt][0], c[nt][1]));
        mx1 = fmaxf(mx1, fmaxf(c[nt][2], c[nt][3]));
    }
    mx0 = fmaxf(mx0, __shfl_xor_sync(0xffffffffu, mx0, 1));
    mx0 = fmaxf(mx0, __shfl_xor_sync(0xffffffffu, mx0, 2));
    mx1 = fmaxf(mx1, __shfl_xor_sync(0xffffffffu, mx1, 1));
    mx1 = fmaxf(mx1, __shfl_xor_sync(0xffffffffu, mx1, 2));
    float s0 = 0.f, s1 = 0.f;
#pragma unroll
    for (int nt = 0; nt < 8; nt++) {
        c[nt][0] = __expf(c[nt][0] - mx0); s0 += c[nt][0];
        c[nt][1] = __expf(c[nt][1] - mx0); s0 += c[nt][1];
        c[nt][2] = __expf(c[nt][2] - mx1); s1 += c[nt][2];
        c[nt][3] = __expf(c[nt][3] - mx1); s1 += c[nt][3];
    }
    s0 += __shfl_xor_sync(0xffffffffu, s0, 1);
    s0 += __shfl_xor_sync(0xffffffffu, s0, 2);
    s1 += __shfl_xor_sync(0xffffffffu, s1, 1);
    s1 += __shfl_xor_sync(0xffffffffu, s1, 2);
    float inv0 = 1.0f / s0, inv1 = 1.0f / s1;
#pragma unroll
    for (int nt = 0; nt < 8; nt++) {
        c[nt][0] *= inv0; c[nt][1] *= inv0;
        c[nt][2] *= inv1; c[nt][3] *= inv1;
    }

    uint32_t pa[4][4];
#pragma unroll
    for (int kt = 0; kt < 4; kt++) {
        pa[kt][0] = packbf2(c[2 * kt][0], c[2 * kt][1]);
        pa[kt][1] = packbf2(c[2 * kt][2], c[2 * kt][3]);
        pa[kt][2] = packbf2(c[2 * kt + 1][0], c[2 * kt + 1][1]);
        pa[kt][3] = packbf2(c[2 * kt + 1][2], c[2 * kt + 1][3]);
    }
    float d[4][4];
#pragma unroll
    for (int nt = 0; nt < 4; nt++)
#pragma unroll
        for (int i = 0; i < 4; i++) d[nt][i] = 0.f;
#pragma unroll
    for (int nt = 0; nt < 4; nt++) {
#pragma unroll
        for (int kt = 0; kt < 4; kt++) {
            uint32_t bf[2];
            bf[0] = *(const uint32_t*)&sVT[(nt * 8 + g) * 72 + kt * 16 + 2 * q4];
            bf[1] = *(const uint32_t*)&sVT[(nt * 8 + g) * 72 + kt * 16 + 8 + 2 * q4];
            mma_bf16v(d[nt], pa[kt], bf);
        }
    }

    size_t ob0 = (size_t)(wi * 64 + i0) * C_DIM + head * 32;
    size_t ob1 = (size_t)(wi * 64 + i1) * C_DIM + head * 32;
#pragma unroll
    for (int nt = 0; nt < 4; nt++) {
        int col = nt * 8 + 2 * q4;
        *(uint32_t*)&g_attnout[ob0 + col] = packbf2(d[nt][0], d[nt][1]);
        *(uint32_t*)&g_attnout[ob1 + col] = packbf2(d[nt][2], d[nt][3]);
    }
}

extern "C" void kernel_launch(void* const* d_in, const int* in_sizes, int n_in,
                              void* d_out, int out_size) {
    const float* x          = (const float*)d_in[0];
    const float* g1         = (const float*)d_in[1];
    const float* b1         = (const float*)d_in[2];
    const float* wqkv       = (const float*)d_in[3];
    const float* bqkv       = (const float*)d_in[4];
    const float* wo         = (const float*)d_in[5];
    const float* bo         = (const float*)d_in[6];
    const float* bias_table = (const float*)d_in[7];
    const float* g2         = (const float*)d_in[8];
    const float* b2         = (const float*)d_in[9];
    const float* w1         = (const float*)d_in[10];
    const float* bm1        = (const float*)d_in[11];
    const float* w2         = (const float*)d_in[12];
    const float* bm2        = (const float*)d_in[13];
    float* out              = (float*)d_out;

    __nv_bfloat16 *wqkvT, *woT, *w1T, *w2T;
    cudaGetSymbolAddress((void**)&wqkvT, g_wqkvT);
    cudaGetSymbolAddress((void**)&woT, g_woT);
    cudaGetSymbolAddress((void**)&w1T, g_w1T);
    cudaGetSymbolAddress((void**)&w2T, g_w2T);

    static int smem_set = 0;
    if (!smem_set) {
        cudaFuncSetAttribute(gemm_bf16, cudaFuncAttributeMaxDynamicSharedMemorySize,
                             GEMM_SMEM_BYTES);
        smem_set = 1;
    }

    // 0. weight prep (one launch)
    prep_all<<<(W0 + W1 + W2 + W3 + 255) / 256, 256>>>(wqkv, wo, w1, w2);
    // 1. LN1 + shift + window partition
    ln_kernel<<<M_TOT / 8, 256>>>(x, g1, b1, 0);
    // 2. QKV projection
    gemm_bf16<<<dim3(576 / 64, M_TOT / 256), 256, GEMM_SMEM_BYTES>>>(wqkvT, bqkv, nullptr, nullptr, C_DIM, 576, 0);
    // 3. windowed attention
    attn_kernel<<<NWIN * HEADS, 128>>>(bias_table);
    // 4. output projection + reverse shift + residual
    gemm_bf16<<<dim3(192 / 64, M_TOT / 256), 256, GEMM_SMEM_BYTES>>>(woT, bo, x, nullptr, C_DIM, C_DIM, 1);
    // 5. LN2
    ln_kernel<<<M_TOT / 8, 256>>>(nullptr, g2, b2, 1);
    // 6. fc1 + gelu
    gemm_bf16<<<dim3(768 / 64, M_TOT / 256), 256, GEMM_SMEM_BYTES>>>(w1T, bm1, nullptr, nullptr, C_DIM, HID, 2);
    // 7. fc2 + residual -> out
    gemm_bf16<<<dim3(192 / 64, M_TOT / 256), 256, GEMM_SMEM_BYTES>>>(w2T, bm2, nullptr, out, HID, C_DIM, 3);
}

// round 15
// speedup vs baseline: 1.2493x; 1.2493x over previous
#include <cuda_runtime.h>
#include <cuda_bf16.h>
#include <math.h>
#include <stdint.h>

// ---------------- problem constants ----------------
#define BATCH 2
#define GRID_DIM 32
#define C_DIM 192
#define HEADS 6
#define HD 32
#define NTOK 64
#define NWIN 1024
#define M_TOT (NWIN * NTOK)
#define HID 768
#define SHIFT_AMT 2

// ---------------- scratch (device globals; no allocs) ----------------
__device__ __nv_bfloat16 g_xw[M_TOT * C_DIM];
__device__ __nv_bfloat16 g_qkv[3 * NWIN * HEADS * NTOK * HD]; // q pre-scaled
__device__ __nv_bfloat16 g_attnout[M_TOT * C_DIM];
__device__ float         g_xo[M_TOT * C_DIM];
__device__ __nv_bfloat16 g_xn2[M_TOT * C_DIM];
__device__ __nv_bfloat16 g_h1[M_TOT * HID];
// transposed bf16 weights [N][K]
__device__ __nv_bfloat16 g_wqkvT[576 * 192];
__device__ __nv_bfloat16 g_woT[192 * 192];
__device__ __nv_bfloat16 g_w1T[768 * 192];
__device__ __nv_bfloat16 g_w2T[192 * 768];
// precomputed (bias + shift-mask) tables: [type 0..7][head][i][j]
__device__ float g_bmask[8 * HEADS * 64 * 64];

// ---------------- helpers ----------------
__device__ __forceinline__ float gelu_exact(float v) {
    return 0.5f * v * (1.0f + erff(v * 0.70710678118654752f));
}
__device__ __forceinline__ void mma_bf16(float (&c)[4], const uint32_t (&a)[4],
                                         const uint32_t b0, const uint32_t b1) {
    asm volatile(
        "mma.sync.aligned.m16n8k16.row.col.f32.bf16.bf16.f32 "
        "{%0,%1,%2,%3}, {%4,%5,%6,%7}, {%8,%9}, {%0,%1,%2,%3};"
        : "+f"(c[0]), "+f"(c[1]), "+f"(c[2]), "+f"(c[3])
        : "r"(a[0]), "r"(a[1]), "r"(a[2]), "r"(a[3]), "r"(b0), "r"(b1));
}
__device__ __forceinline__ void mma_bf16v(float (&c)[4], const uint32_t (&a)[4],
                                          const uint32_t (&b)[2]) {
    mma_bf16(c, a, b[0], b[1]);
}
__device__ __forceinline__ void ldm_x4(uint32_t (&r)[4], uint32_t addr) {
    asm volatile("ldmatrix.sync.aligned.m8n8.x4.shared.b16 {%0,%1,%2,%3}, [%4];"
                 : "=r"(r[0]), "=r"(r[1]), "=r"(r[2]), "=r"(r[3]) : "r"(addr));
}
__device__ __forceinline__ uint32_t packbf2(float a, float b) {
    __nv_bfloat162 t = __floats2bfloat162_rn(a, b);
    return *(uint32_t*)&t;
}
__device__ __forceinline__ uint32_t smem_u32(const void* p) {
    return (uint32_t)__cvta_generic_to_shared(p);
}
#define CP16(dst, src) \
    asm volatile("cp.async.cg.shared.global [%0], [%1], 16;" :: "r"(dst), "l"(src))
#define CP_COMMIT() asm volatile("cp.async.commit_group;")
#define CP_WAIT2()  asm volatile("cp.async.wait_group 2;")

__device__ __forceinline__ int winrow_to_orig(int t) {
    int wi = t >> 6, n = t & 63;
    int b  = wi >> 9;
    int Hb = (wi >> 6) & 7, Wb = (wi >> 3) & 7, Db = wi & 7;
    int i = n >> 4, j = (n >> 2) & 3, k = n & 3;
    int h = ((Hb << 2) + i + SHIFT_AMT) & 31;
    int w = ((Wb << 2) + j + SHIFT_AMT) & 31;
    int d = ((Db << 2) + k + SHIFT_AMT) & 31;
    return (((b * 32 + h) * 32 + w) * 32 + d);
}

// ---------------- weight prep: all four fp32 [K][N] -> bf16 [N][K] --------
#define W0 (576 * 192)
#define W1 (192 * 192)
#define W2 (768 * 192)
#define W3 (192 * 768)
__global__ __launch_bounds__(256) void prep_all(const float* __restrict__ wqkv,
                                                const float* __restrict__ wo,
                                                const float* __restrict__ w1,
                                                const float* __restrict__ w2) {
    int i = blockIdx.x * 256 + threadIdx.x;
    const float* src;
    __nv_bfloat16* dst;
    int K, N;
    if (i < W0)                       { src = wqkv; dst = g_wqkvT; K = 192; N = 576; }
    else if ((i -= W0) < W1)          { src = wo;   dst = g_woT;   K = 192; N = 192; }
    else if ((i -= W1) < W2)          { src = w1;   dst = g_w1T;   K = 192; N = 768; }
    else if ((i -= W2) < W3)          { src = w2;   dst = g_w2T;   K = 768; N = 192; }
    else return;
    int n = i / K, k = i - n * K;
    dst[i] = __float2bfloat16(src[k * N + n]);
}

// ---------------- bias+mask table precompute ----------------
// g_bmask[((type*HEADS+head)*64+i)*64+j] = bias_table[rel(i,j)][head] + mask(type,i,j)
__global__ __launch_bounds__(256) void prep_bmask(const float* __restrict__ bias_table) {
    int idx = blockIdx.x * 256 + threadIdx.x;
    if (idx >= 8 * HEADS * 64 * 64) return;
    int j = idx & 63;
    int i = (idx >> 6) & 63;
    int head = (idx >> 12) % HEADS;
    int type = idx / (4096 * HEADS);
    int ih = i >> 4, iw = (i >> 2) & 3, id = i & 3;
    int jh = j >> 4, jw = (j >> 2) & 3, jd = j & 3;
    int rel = ((ih - jh + 3) * 7 + (iw - jw + 3)) * 7 + (id - jd + 3);
    int rhi = (type & 4) ? (ih >= 2 ? 2 : 1) : 0;
    int rwi = (type & 2) ? (iw >= 2 ? 2 : 1) : 0;
    int rdi = (type & 1) ? (id >= 2 ? 2 : 1) : 0;
    int rhj = (type & 4) ? (jh >= 2 ? 2 : 1) : 0;
    int rwj = (type & 2) ? (jw >= 2 ? 2 : 1) : 0;
    int rdj = (type & 1) ? (jd >= 2 ? 2 : 1) : 0;
    int ri = rhi * 9 + rwi * 3 + rdi, rj = rhj * 9 + rwj * 3 + rdj;
    float m = (ri != rj) ? -100.0f : 0.0f;
    g_bmask[idx] = bias_table[rel * HEADS + head] + m;
}

// ---------------- LN kernels (warp per token), bf16 output ----------------
__global__ __launch_bounds__(256) void ln_kernel(const float* __restrict__ xin,
                                                 const float* __restrict__ gma,
                                                 const float* __restrict__ bta,
                                                 int mode) {
    int warp = threadIdx.x >> 5, lane = threadIdx.x & 31;
    int t = blockIdx.x * 8 + warp;
    const float* src;
    __nv_bfloat16* dst;
    if (mode == 0) {
        src = xin + (size_t)winrow_to_orig(t) * C_DIM;
        dst = g_xw + (size_t)t * C_DIM;
    } else {
        src = g_xo + (size_t)t * C_DIM;
        dst = g_xn2 + (size_t)t * C_DIM;
    }
    float v[6];
    float s = 0.f;
#pragma unroll
    for (int k = 0; k < 6; k++) { v[k] = src[lane + 32 * k]; s += v[k]; }
#pragma unroll
    for (int o = 16; o > 0; o >>= 1) s += __shfl_xor_sync(0xffffffffu, s, o);
    float mean = s * (1.0f / C_DIM);
    float q = 0.f;
#pragma unroll
    for (int k = 0; k < 6; k++) { float d = v[k] - mean; q += d * d; }
#pragma unroll
    for (int o = 16; o > 0; o >>= 1) q += __shfl_xor_sync(0xffffffffu, q, o);
    float rstd = rsqrtf(q * (1.0f / C_DIM) + 1e-5f);
#pragma unroll
    for (int k = 0; k < 6; k++) {
        int c = lane + 32 * k;
        dst[c] = __float2bfloat16((v[k] - mean) * rstd * gma[c] + bta[c]);
    }
}

// ---------------- bf16 GEMM: 128x64 tile, 4-stage cp.async, hoisted ldsm ---
// 256 threads = 8 warps (4x2), warp tile 32x32.
__global__ __launch_bounds__(256) void gemm_bf16(const __nv_bfloat16* __restrict__ BwT,
                                                 const float* __restrict__ bias,
                                                 const float* __restrict__ xres,
                                                 float* __restrict__ dout,
                                                 int K, int N, int mode) {
    const __nv_bfloat16* A = (mode == 0) ? g_xw
                           : (mode == 1) ? g_attnout
                           : (mode == 2) ? g_xn2
                                         : g_h1;
    __shared__ __nv_bfloat16 AsH[4][128 * 40];   // [m][k], stride 40
    __shared__ __nv_bfloat16 BsH[4][64 * 40];    // [n][k], stride 40

    int tid = threadIdx.x;
    int warp = tid >> 5, lane = tid & 31;
    int gid = lane >> 2, tig = lane & 3;
    int warpM = warp & 3, warpN = warp >> 2;
    int row0 = blockIdx.y * 128, col0 = blockIdx.x * 64;

    // cp.async coordinates
    int aRow = tid >> 1, aCol = (tid & 1) * 16;
    int bRow = tid >> 2, bCol = (tid & 3) * 8;
    const __nv_bfloat16* aSrc = A + (size_t)(row0 + aRow) * K + aCol;
    const __nv_bfloat16* bSrc = BwT + (size_t)(col0 + bRow) * K + bCol;

    // ldmatrix offsets
    int aKoff = (lane >> 4) << 3;
    int aLdmRow[2];
#pragma unroll
    for (int mt = 0; mt < 2; mt++)
        aLdmRow[mt] = (warpM * 32 + mt * 16 + (lane & 15)) * 40 + aKoff;
    int bKoff = ((lane >> 3) & 1) << 3;
    int bLdmRow = (warpN * 32 + ((lane >> 4) << 3) + (lane & 7)) * 40 + bKoff;

    int NK = K >> 5;

    float acc[2][4][4];
#pragma unroll
    for (int mt = 0; mt < 2; mt++)
#pragma unroll
        for (int nt = 0; nt < 4; nt++)
#pragma unroll
            for (int i = 0; i < 4; i++) acc[mt][nt][i] = 0.f;

    // prologue: stages 0,1,2
#pragma unroll
    for (int s = 0; s < 3; s++) {
        if (s < NK) {
            uint32_t ad = smem_u32(&AsH[s][aRow * 40 + aCol]);
            CP16(ad, aSrc + s * 32);
            CP16(ad + 16, aSrc + s * 32 + 8);
            uint32_t bd = smem_u32(&BsH[s][bRow * 40 + bCol]);
            CP16(bd, bSrc + s * 32);
        }
        CP_COMMIT();
    }

    for (int ki = 0; ki < NK; ki++) {
        CP_WAIT2();
        __syncthreads();
        int kn = ki + 3;
        if (kn < NK) {
            int st = kn & 3;
            uint32_t ad = smem_u32(&AsH[st][aRow * 40 + aCol]);
            CP16(ad, aSrc + kn * 32);
            CP16(ad + 16, aSrc + kn * 32 + 8);
            uint32_t bd = smem_u32(&BsH[st][bRow * 40 + bCol]);
            CP16(bd, bSrc + kn * 32);
        }
        CP_COMMIT();

        int s = ki & 3;
        uint32_t aBase = smem_u32(&AsH[s][0]);
        uint32_t bBase = smem_u32(&BsH[s][0]);
        // hoist ALL fragment loads for this k32 step, then do all mma
        uint32_t afr[2][2][4];   // [kk][mt]
        uint32_t bfr[2][2][4];   // [kk][p]
#pragma unroll
        for (int k2 = 0; k2 < 2; k2++) {
#pragma unroll
            for (int mt = 0; mt < 2; mt++)
                ldm_x4(afr[k2][mt], aBase + (aLdmRow[mt] + k2 * 16) * 2);
#pragma unroll
            for (int p = 0; p < 2; p++)
                ldm_x4(bfr[k2][p], bBase + (bLdmRow + p * 16 * 40 + k2 * 16) * 2);
        }
#pragma unroll
        for (int k2 = 0; k2 < 2; k2++)
#pragma unroll
            for (int p = 0; p < 2; p++)
#pragma unroll
                for (int mt = 0; mt < 2; mt++) {
                    mma_bf16(acc[mt][2 * p + 0], afr[k2][mt], bfr[k2][p][0], bfr[k2][p][1]);
                    mma_bf16(acc[mt][2 * p + 1], afr[k2][mt], bfr[k2][p][2], bfr[k2][p][3]);
                }
    }

    const float QK_SCALE = 0.17677669529663687f;
#pragma unroll
    for (int mt = 0; mt < 2; mt++) {
        int rbase = row0 + warpM * 32 + mt * 16 + gid;
#pragma unroll
        for (int half = 0; half < 2; half++) {
            int row = rbase + half * 8;
            int obase1 = 0;
            if (mode == 1) obase1 = winrow_to_orig(row) * C_DIM;
#pragma unroll
            for (int nt = 0; nt < 4; nt++) {
                int col = col0 + warpN * 32 + nt * 8 + 2 * tig;
                float v0 = acc[mt][nt][half * 2 + 0] + bias[col];
                float v1 = acc[mt][nt][half * 2 + 1] + bias[col + 1];
                if (mode == 0) {
                    int wi = row >> 6, n = row & 63;
                    int which = col / 192;
                    int rem = col - which * 192;
                    int head = rem >> 5, hdi = rem & 31;
                    float sc = (which == 0) ? QK_SCALE : 1.0f;
                    uint32_t* p = (uint32_t*)&g_qkv[(((which * NWIN + wi) * HEADS + head) << 11) + (n << 5) + hdi];
                    *p = packbf2(v0 * sc, v1 * sc);
                } else if (mode == 1) {
                    float* p = &g_xo[obase1 + col];
                    const float* r = &xres[obase1 + col];
                    *(float2*)p = make_float2(v0 + r[0], v1 + r[1]);
                } else if (mode == 2) {
                    uint32_t* p = (uint32_t*)&g_h1[(size_t)row * HID + col];
                    *p = packbf2(gelu_exact(v0), gelu_exact(v1));
                } else {
                    size_t o = (size_t)row * C_DIM + col;
                    *(float2*)&dout[o] = make_float2(v0 + g_xo[o], v1 + g_xo[o + 1]);
                }
            }
        }
    }
}

// ---------------- attention: tensor-core, 1 block per (window, head) -------
__global__ __launch_bounds__(128) void attn_kernel() {
    __shared__ __nv_bfloat16 sQ[64 * 40];
    __shared__ __nv_bfloat16 sK[64 * 40];
    __shared__ __nv_bfloat16 sVT[32 * 72];

    int wi = blockIdx.x / HEADS, head = blockIdx.x % HEADS;
    int tid = threadIdx.x;
    int warp = tid >> 5, lane = tid & 31;
    int g = lane >> 2, q4 = lane & 3;

    const __nv_bfloat16* Qg = g_qkv + (((0 * NWIN + wi) * HEADS + head) << 11);
    const __nv_bfloat16* Kg = g_qkv + (((1 * NWIN + wi) * HEADS + head) << 11);
    const __nv_bfloat16* Vg = g_qkv + (((2 * NWIN + wi) * HEADS + head) << 11);

#pragma unroll
    for (int i = tid; i < 256; i += 128) {
        int r = i >> 2, c = (i & 3) * 8;
        *(uint4*)&sQ[r * 40 + c] = *(const uint4*)&Qg[r * 32 + c];
        *(uint4*)&sK[r * 40 + c] = *(const uint4*)&Kg[r * 32 + c];
        uint4 v = *(const uint4*)&Vg[r * 32 + c];
        __nv_bfloat16 tmp[8];
        *(uint4*)tmp = v;
#pragma unroll
        for (int j = 0; j < 8; j++) sVT[(c + j) * 72 + r] = tmp[j];
    }
    __syncthreads();

    int m0 = warp * 16;
    uint32_t af[2][4];
#pragma unroll
    for (int kt = 0; kt < 2; kt++) {
        int kk = kt * 16;
        af[kt][0] = *(const uint32_t*)&sQ[(m0 + g) * 40 + kk + 2 * q4];
        af[kt][1] = *(const uint32_t*)&sQ[(m0 + g + 8) * 40 + kk + 2 * q4];
        af[kt][2] = *(const uint32_t*)&sQ[(m0 + g) * 40 + kk + 8 + 2 * q4];
        af[kt][3] = *(const uint32_t*)&sQ[(m0 + g + 8) * 40 + kk + 8 + 2 * q4];
    }
    float c[8][4];
#pragma unroll
    for (int nt = 0; nt < 8; nt++)
#pragma unroll
        for (int i = 0; i < 4; i++) c[nt][i] = 0.f;
#pragma unroll
    for (int nt = 0; nt < 8; nt++) {
#pragma unroll
        for (int kt = 0; kt < 2; kt++) {
            uint32_t bf[2];
            bf[0] = *(const uint32_t*)&sK[(nt * 8 + g) * 40 + kt * 16 + 2 * q4];
            bf[1] = *(const uint32_t*)&sK[(nt * 8 + g) * 40 + kt * 16 + 8 + 2 * q4];
            mma_bf16v(c[nt], af[kt], bf);
        }
    }

    // precomputed bias+mask: type from window coords
    int Hb = (wi >> 6) & 7, Wb = (wi >> 3) & 7, Db = wi & 7;
    int type = ((Hb == 7) << 2) | ((Wb == 7) << 1) | (Db == 7);
    int i0 = m0 + g, i1 = i0 + 8;
    const float* T = g_bmask + ((type * HEADS + head) << 12);
    const float* Ti0 = T + i0 * 64 + 2 * q4;
    const float* Ti1 = T + i1 * 64 + 2 * q4;
#pragma unroll
    for (int nt = 0; nt < 8; nt++) {
        float2 t0 = *(const float2*)&Ti0[nt * 8];
        float2 t1 = *(const float2*)&Ti1[nt * 8];
        c[nt][0] += t0.x; c[nt][1] += t0.y;
        c[nt][2] += t1.x; c[nt][3] += t1.y;
    }

    float mx0 = -1e30f, mx1 = -1e30f;
#pragma unroll
    for (int nt = 0; nt < 8; nt++) {
        mx0 = fmaxf(mx0, fmaxf(c[nt][0], c[nt][1]));
        mx1 = fmaxf(mx1, fmaxf(c[nt][2], c[nt][3]));
    }
    mx0 = fmaxf(mx0, __shfl_xor_sync(0xffffffffu, mx0, 1));
    mx0 = fmaxf(mx0, __shfl_xor_sync(0xffffffffu, mx0, 2));
    mx1 = fmaxf(mx1, __shfl_xor_sync(0xffffffffu, mx1, 1));
    mx1 = fmaxf(mx1, __shfl_xor_sync(0xffffffffu, mx1, 2));
    float s0 = 0.f, s1 = 0.f;
#pragma unroll
    for (int nt = 0; nt < 8; nt++) {
        c[nt][0] = __expf(c[nt][0] - mx0); s0 += c[nt][0];
        c[nt][1] = __expf(c[nt][1] - mx0); s0 += c[nt][1];
        c[nt][2] = __expf(c[nt][2] - mx1); s1 += c[nt][2];
        c[nt][3] = __expf(c[nt][3] - mx1); s1 += c[nt][3];
    }
    s0 += __shfl_xor_sync(0xffffffffu, s0, 1);
    s0 += __shfl_xor_sync(0xffffffffu, s0, 2);
    s1 += __shfl_xor_sync(0xffffffffu, s1, 1);
    s1 += __shfl_xor_sync(0xffffffffu, s1, 2);
    float inv0 = 1.0f / s0, inv1 = 1.0f / s1;
#pragma unroll
    for (int nt = 0; nt < 8; nt++) {
        c[nt][0] *= inv0; c[nt][1] *= inv0;
        c[nt][2] *= inv1; c[nt][3] *= inv1;
    }

    uint32_t pa[4][4];
#pragma unroll
    for (int kt = 0; kt < 4; kt++) {
        pa[kt][0] = packbf2(c[2 * kt][0], c[2 * kt][1]);
        pa[kt][1] = packbf2(c[2 * kt][2], c[2 * kt][3]);
        pa[kt][2] = packbf2(c[2 * kt + 1][0], c[2 * kt + 1][1]);
        pa[kt][3] = packbf2(c[2 * kt + 1][2], c[2 * kt + 1][3]);
    }
    float d[4][4];
#pragma unroll
    for (int nt = 0; nt < 4; nt++)
#pragma unroll
        for (int i = 0; i < 4; i++) d[nt][i] = 0.f;
#pragma unroll
    for (int nt = 0; nt < 4; nt++) {
#pragma unroll
        for (int kt = 0; kt < 4; kt++) {
            uint32_t bf[2];
            bf[0] = *(const uint32_t*)&sVT[(nt * 8 + g) * 72 + kt * 16 + 2 * q4];
            bf[1] = *(const uint32_t*)&sVT[(nt * 8 + g) * 72 + kt * 16 + 8 + 2 * q4];
            mma_bf16v(d[nt], pa[kt], bf);
        }
    }

    size_t ob0 = (size_t)(wi * 64 + i0) * C_DIM + head * 32;
    size_t ob1 = (size_t)(wi * 64 + i1) * C_DIM + head * 32;
#pragma unroll
    for (int nt = 0; nt < 4; nt++) {
        int col = nt * 8 + 2 * q4;
        *(uint32_t*)&g_attnout[ob0 + col] = packbf2(d[nt][0], d[nt][1]);
        *(uint32_t*)&g_attnout[ob1 + col] = packbf2(d[nt][2], d[nt][3]);
    }
}

extern "C" void kernel_launch(void* const* d_in, const int* in_sizes, int n_in,
                              void* d_out, int out_size) {
    const float* x          = (const float*)d_in[0];
    const float* g1         = (const float*)d_in[1];
    const float* b1         = (const float*)d_in[2];
    const float* wqkv       = (const float*)d_in[3];
    const float* bqkv       = (const float*)d_in[4];
    const float* wo         = (const float*)d_in[5];
    const float* bo         = (const float*)d_in[6];
    const float* bias_table = (const float*)d_in[7];
    const float* g2         = (const float*)d_in[8];
    const float* b2         = (const float*)d_in[9];
    const float* w1         = (const float*)d_in[10];
    const float* bm1        = (const float*)d_in[11];
    const float* w2         = (const float*)d_in[12];
    const float* bm2        = (const float*)d_in[13];
    float* out              = (float*)d_out;

    __nv_bfloat16 *wqkvT, *woT, *w1T, *w2T;
    cudaGetSymbolAddress((void**)&wqkvT, g_wqkvT);
    cudaGetSymbolAddress((void**)&woT, g_woT);
    cudaGetSymbolAddress((void**)&w1T, g_w1T);
    cudaGetSymbolAddress((void**)&w2T, g_w2T);

    // 0. weight prep + bias/mask table
    prep_all<<<(W0 + W1 + W2 + W3 + 255) / 256, 256>>>(wqkv, wo, w1, w2);
    prep_bmask<<<(8 * HEADS * 64 * 64 + 255) / 256, 256>>>(bias_table);
    // 1. LN1 + shift + window partition
    ln_kernel<<<M_TOT / 8, 256>>>(x, g1, b1, 0);
    // 2. QKV projection
    gemm_bf16<<<dim3(576 / 64, M_TOT / 128), 256>>>(wqkvT, bqkv, nullptr, nullptr, C_DIM, 576, 0);
    // 3. windowed attention
    attn_kernel<<<NWIN * HEADS, 128>>>();
    // 4. output projection + reverse shift + residual
    gemm_bf16<<<dim3(192 / 64, M_TOT / 128), 256>>>(woT, bo, x, nullptr, C_DIM, C_DIM, 1);
    // 5. LN2
    ln_kernel<<<M_TOT / 8, 256>>>(nullptr, g2, b2, 1);
    // 6. fc1 + gelu
    gemm_bf16<<<dim3(768 / 64, M_TOT / 128), 256>>>(w1T, bm1, nullptr, nullptr, C_DIM, HID, 2);
    // 7. fc2 + residual -> out
    gemm_bf16<<<dim3(192 / 64, M_TOT / 128), 256>>>(w2T, bm2, nullptr, out, HID, C_DIM, 3);
}